// round 1
// baseline (speedup 1.0000x reference)
#include <cuda_runtime.h>

#define M_TOTAL 8192
#define NPT 128
#define NTILES 64
#define RESULT_ELEMS (M_TOTAL * 7)   // 57344

// scratch (no allocations allowed)
__device__ unsigned long long g_keys[M_TOTAL];
__device__ float g_rec[M_TOTAL * 8];

// ---------------------------------------------------------------------------
// Kernel A: per-tile transform + sort + greedy NMS
// ---------------------------------------------------------------------------
__global__ void __launch_bounds__(NPT) tile_nms_kernel(const float* __restrict__ tr,
                                                       const int* __restrict__ tp) {
    const int tile = blockIdx.x;
    const int t = threadIdx.x;
    const int g = tile * NPT + t;

    __shared__ float s_shift[NPT][4];          // shifted (class-offset) clipped boxes, pre-sort order
    __shared__ float s_out[NPT][7];            // output record (clipped box, score, label, growth)
    __shared__ unsigned char s_valid[NPT];
    __shared__ unsigned long long s_key[NPT];
    __shared__ int s_perm[NPT];
    __shared__ float s_sbox[NPT][4];           // sorted shifted boxes
    __shared__ float s_area[NPT];              // sorted areas
    __shared__ unsigned char s_keep[NPT];

    // ---- load + transform (mirror reference fp32 op-for-op) ----
    const float* r = tr + (size_t)g * 7;
    float b0 = r[0], b1 = r[1], b2 = r[2], b3 = r[3];
    const float score  = r[4];
    const float labelf = r[5];
    const float growth = r[6];
    const float hs = (float)tp[tile * 4 + 0];  // h_start -> cols 1,3
    const float ws = (float)tp[tile * 4 + 2];  // w_start -> cols 0,2
    b0 = fminf(fmaxf(__fadd_rn(b0, ws), 0.0f), 4096.0f);
    b1 = fminf(fmaxf(__fadd_rn(b1, hs), 0.0f), 4096.0f);
    b2 = fminf(fmaxf(__fadd_rn(b2, ws), 0.0f), 4096.0f);
    b3 = fminf(fmaxf(__fadd_rn(b3, hs), 0.0f), 4096.0f);

    const bool valid = score > 0.05f;
    const float sk = valid ? score : __fsub_rn(score, 1e9f);
    unsigned int ob = __float_as_uint(sk);
    ob = (ob & 0x80000000u) ? ~ob : (ob | 0x80000000u);   // monotone float->uint
    // descending score, ties by ascending global index (JAX stable argsort)
    const unsigned long long key =
        ((unsigned long long)ob << 32) | (unsigned int)(~(unsigned int)g);

    const float shift = __fmul_rn(labelf, 8192.0f);        // 2*IMAGE_SIZE
    s_shift[t][0] = __fadd_rn(b0, shift);
    s_shift[t][1] = __fadd_rn(b1, shift);
    s_shift[t][2] = __fadd_rn(b2, shift);
    s_shift[t][3] = __fadd_rn(b3, shift);
    s_out[t][0] = b0; s_out[t][1] = b1; s_out[t][2] = b2; s_out[t][3] = b3;
    s_out[t][4] = score; s_out[t][5] = labelf; s_out[t][6] = growth;
    s_valid[t] = valid ? 1 : 0;
    s_key[t] = key;
    s_perm[t] = t;
    __syncthreads();

    // ---- bitonic sort, descending, 128 elements ----
    for (int k = 2; k <= NPT; k <<= 1) {
        for (int j = k >> 1; j > 0; j >>= 1) {
            const int ixj = t ^ j;
            if (ixj > t) {
                const unsigned long long a = s_key[t];
                const unsigned long long b = s_key[ixj];
                const bool swp = ((t & k) == 0) ? (a < b) : (a > b);
                if (swp) {
                    s_key[t] = b; s_key[ixj] = a;
                    const int pa = s_perm[t];
                    s_perm[t] = s_perm[ixj]; s_perm[ixj] = pa;
                }
            }
            __syncthreads();
        }
    }

    // ---- gather my sorted record ----
    const int p = s_perm[t];
    const float x0 = s_shift[p][0], x1c = s_shift[p][1];
    const float x2 = s_shift[p][2], x3 = s_shift[p][3];
    float o0 = s_out[p][0], o1 = s_out[p][1], o2 = s_out[p][2], o3 = s_out[p][3];
    float o4 = s_out[p][4], o5 = s_out[p][5], o6 = s_out[p][6];
    int my_keep = s_valid[p];
    const unsigned long long mykey = s_key[t];
    __syncthreads();

    s_sbox[t][0] = x0; s_sbox[t][1] = x1c; s_sbox[t][2] = x2; s_sbox[t][3] = x3;
    const float myarea = __fmul_rn(__fsub_rn(x2, x0), __fsub_rn(x3, x1c));
    s_area[t] = myarea;
    __syncthreads();

    // ---- greedy sequential collect (reference semantics) ----
    for (int i = 0; i < NPT; i++) {
        if (t == i) s_keep[i] = (unsigned char)my_keep;   // final by now (only i' < i update it)
        __syncthreads();
        if (t > i && my_keep && s_keep[i]) {
            const float i0 = s_sbox[i][0], i1 = s_sbox[i][1];
            const float i2 = s_sbox[i][2], i3 = s_sbox[i][3];
            const float ltx = fmaxf(i0, x0),  lty = fmaxf(i1, x1c);
            const float rbx = fminf(i2, x2),  rby = fminf(i3, x3);
            const float wx = fmaxf(__fsub_rn(rbx, ltx), 0.0f);
            const float wy = fmaxf(__fsub_rn(rby, lty), 0.0f);
            const float inter = __fmul_rn(wx, wy);
            const float uni = __fsub_rn(__fadd_rn(s_area[i], myarea), inter);
            const float iou = __fdiv_rn(inter, __fadd_rn(uni, 1e-8f));
            if (iou > 0.5f) my_keep = 0;
        }
    }

    // ---- write per-tile sorted outputs ----
    g_keys[g] = mykey;
    float* gr = g_rec + (size_t)g * 8;
    gr[0] = o0; gr[1] = o1; gr[2] = o2; gr[3] = o3;
    gr[4] = o4; gr[5] = o5; gr[6] = o6;
    gr[7] = my_keep ? 1.0f : 0.0f;
}

// ---------------------------------------------------------------------------
// Kernel B: global rank via 63 binary searches, then scatter
// ---------------------------------------------------------------------------
__global__ void __launch_bounds__(256) rank_scatter_kernel(float* __restrict__ out,
                                                           int writeKeep) {
    const int e = blockIdx.x * blockDim.x + threadIdx.x;
    if (e >= M_TOTAL) return;

    const unsigned long long k = g_keys[e];
    const int myTile = e >> 7;
    int rank = e & 127;

    #pragma unroll 8
    for (int t2 = 0; t2 < NTILES; t2++) {
        if (t2 == myTile) continue;
        const unsigned long long* a = g_keys + t2 * NPT;
        // branchless lower-bound: count of keys strictly greater than k (array descending)
        int lo = 0;
        #pragma unroll
        for (int half = 64; half >= 1; half >>= 1) {
            if (a[lo + half - 1] > k) lo += half;
        }
        rank += lo;
    }

    const float* gr = g_rec + (size_t)e * 8;
    const float keepf = gr[7];
    float* o = out + (size_t)rank * 7;
    o[0] = gr[0] * keepf;
    o[1] = gr[1] * keepf;
    o[2] = gr[2] * keepf;
    o[3] = gr[3] * keepf;
    o[4] = gr[4] * keepf;
    o[5] = gr[5] * keepf;
    o[6] = gr[6] * keepf;
    if (writeKeep) out[RESULT_ELEMS + rank] = keepf;
}

// tail zero-fill for any unexpected out_size layout
__global__ void fill_zero_kernel(float* __restrict__ out, int start, int end) {
    int i = start + blockIdx.x * blockDim.x + threadIdx.x;
    if (i < end) out[i] = 0.0f;
}

// ---------------------------------------------------------------------------
extern "C" void kernel_launch(void* const* d_in, const int* in_sizes, int n_in,
                              void* d_out, int out_size) {
    const float* tr = (const float*)d_in[0];   // tile_results (64,128,7) f32
    const int*   tp = (const int*)d_in[1];     // tile_positions (64,4) i32
    float* out = (float*)d_out;

    tile_nms_kernel<<<NTILES, NPT>>>(tr, tp);

    // defensively zero anything past the result block we might not cover
    if (out_size > RESULT_ELEMS) {
        const int tail = out_size - RESULT_ELEMS;
        fill_zero_kernel<<<(tail + 255) / 256, 256>>>(out, RESULT_ELEMS, out_size);
    }

    const int writeKeep = (out_size >= RESULT_ELEMS + M_TOTAL) ? 1 : 0;
    rank_scatter_kernel<<<(M_TOTAL + 255) / 256, 256>>>(out, writeKeep);
}

// round 2
// speedup vs baseline: 3.5418x; 3.5418x over previous
#include <cuda_runtime.h>

#define M_TOTAL 8192
#define NPT 128
#define NTILES 64
#define RESULT_ELEMS (M_TOTAL * 7)   // 57344

// scratch (no device allocations allowed)
__device__ unsigned long long g_keys[M_TOTAL];      // sorted-per-tile keys
__device__ float4 g_rec4[M_TOTAL * 2];              // sorted-per-tile records (8 floats, 7 used)
__device__ unsigned int g_keepmask[NTILES * 4];     // per-tile keep bitmask (sorted order)

// ---------------------------------------------------------------------------
// Kernel A: per-tile transform + rank-sort + parallel IoU matrix + serial reduce
// ---------------------------------------------------------------------------
__global__ void __launch_bounds__(512) tile_nms_kernel(const float* __restrict__ tr,
                                                       const int* __restrict__ tp) {
    const int tile = blockIdx.x;
    const int tid = threadIdx.x;

    __shared__ unsigned long long s_keyraw[NPT];
    __shared__ float4 s_sbox[NPT];          // sorted shifted boxes
    __shared__ float s_area[NPT];           // sorted areas
    __shared__ unsigned int s_validmask[4]; // valid bits, sorted order
    __shared__ uint4 s_sup[NPT];            // suppression bitmask per sorted row

    // ---- phase 1: load + transform (t < 128) ----
    float b0, b1, b2, b3, score, labelf, growth, area;
    float x0, x1c, x2, x3;
    unsigned long long mykey = 0;
    int valid = 0;

    if (tid < 4) s_validmask[tid] = 0;

    if (tid < NPT) {
        const int g = tile * NPT + tid;
        const float* r = tr + (size_t)g * 7;
        b0 = r[0]; b1 = r[1]; b2 = r[2]; b3 = r[3];
        score = r[4]; labelf = r[5]; growth = r[6];
        const float hs = (float)tp[tile * 4 + 0];  // h_start -> cols 1,3
        const float ws = (float)tp[tile * 4 + 2];  // w_start -> cols 0,2
        b0 = fminf(fmaxf(__fadd_rn(b0, ws), 0.0f), 4096.0f);
        b1 = fminf(fmaxf(__fadd_rn(b1, hs), 0.0f), 4096.0f);
        b2 = fminf(fmaxf(__fadd_rn(b2, ws), 0.0f), 4096.0f);
        b3 = fminf(fmaxf(__fadd_rn(b3, hs), 0.0f), 4096.0f);

        valid = (score > 0.05f) ? 1 : 0;
        const float sk = valid ? score : __fsub_rn(score, 1e9f);
        unsigned int ob = __float_as_uint(sk);
        ob = (ob & 0x80000000u) ? ~ob : (ob | 0x80000000u);  // monotone float->uint
        // descending score, ties by ascending global index (stable argsort)
        mykey = ((unsigned long long)ob << 32) | (unsigned int)(~(unsigned int)g);
        s_keyraw[tid] = mykey;

        const float shift = __fmul_rn(labelf, 8192.0f);      // 2*IMAGE_SIZE
        x0  = __fadd_rn(b0, shift);
        x1c = __fadd_rn(b1, shift);
        x2  = __fadd_rn(b2, shift);
        x3  = __fadd_rn(b3, shift);
        area = __fmul_rn(__fsub_rn(x2, x0), __fsub_rn(x3, x1c));
    }
    __syncthreads();

    // ---- phase 2: rank-sort (t < 128), scatter into sorted arrays ----
    if (tid < NPT) {
        int rank = 0;
        #pragma unroll 16
        for (int j = 0; j < NPT; j++) rank += (s_keyraw[j] > mykey) ? 1 : 0;

        s_sbox[rank] = make_float4(x0, x1c, x2, x3);
        s_area[rank] = area;
        atomicOr(&s_validmask[rank >> 5], (unsigned int)valid << (rank & 31));

        const int gs = tile * NPT + rank;
        g_keys[gs] = mykey;
        g_rec4[gs * 2 + 0] = make_float4(b0, b1, b2, b3);
        g_rec4[gs * 2 + 1] = make_float4(score, labelf, growth, 0.0f);
    }
    __syncthreads();

    // ---- phase 3: suppression matrix (all 512 threads; thread = (row, word)) ----
    {
        const int i = tid >> 2;
        const int w = tid & 3;
        const float4 bi = s_sbox[i];
        const float ai = s_area[i];
        unsigned int word = 0;
        #pragma unroll 8
        for (int jj = 0; jj < 32; jj++) {
            const int j = (w << 5) + jj;
            const float4 bj = s_sbox[j];
            const float ltx = fmaxf(bi.x, bj.x), lty = fmaxf(bi.y, bj.y);
            const float rbx = fminf(bi.z, bj.z), rby = fminf(bi.w, bj.w);
            const float wx = fmaxf(__fsub_rn(rbx, ltx), 0.0f);
            const float wy = fmaxf(__fsub_rn(rby, lty), 0.0f);
            const float inter = __fmul_rn(wx, wy);
            const float uni = __fsub_rn(__fadd_rn(ai, s_area[j]), inter);
            const float iou = __fdiv_rn(inter, __fadd_rn(uni, 1e-8f));
            if ((j > i) && (iou > 0.5f)) word |= (1u << jj);
        }
        ((unsigned int*)&s_sup[i])[w] = word;
    }
    __syncthreads();

    // ---- phase 4: sequential greedy reduce (single thread, all in smem/regs) ----
    if (tid == 0) {
        unsigned int k0 = s_validmask[0], k1 = s_validmask[1];
        unsigned int k2 = s_validmask[2], k3 = s_validmask[3];
        unsigned int kw[4];
        kw[0] = k0; kw[1] = k1; kw[2] = k2; kw[3] = k3;
        for (int i = 0; i < NPT; i++) {
            if ((kw[i >> 5] >> (i & 31)) & 1u) {
                const uint4 s = s_sup[i];
                kw[0] &= ~s.x; kw[1] &= ~s.y; kw[2] &= ~s.z; kw[3] &= ~s.w;
            }
        }
        g_keepmask[tile * 4 + 0] = kw[0];
        g_keepmask[tile * 4 + 1] = kw[1];
        g_keepmask[tile * 4 + 2] = kw[2];
        g_keepmask[tile * 4 + 3] = kw[3];
    }
}

// ---------------------------------------------------------------------------
// Kernel B: global rank via 64 binary searches over smem-cached keys, scatter
// ---------------------------------------------------------------------------
extern __shared__ unsigned long long sk[];  // 8192 keys = 64KB

__global__ void __launch_bounds__(NPT) rank_scatter_kernel(float* __restrict__ out,
                                                           int writeKeep) {
    const int tid = threadIdx.x;

    // cache all keys
    #pragma unroll 16
    for (int idx = tid; idx < M_TOTAL; idx += NPT) sk[idx] = g_keys[idx];
    __syncthreads();

    const int e = blockIdx.x * NPT + tid;
    const unsigned long long k = sk[e];
    const int r_local = e & 127;
    const int myTile = e >> 7;

    // global rank = sum over ALL tiles of count(keys > k); own tile contributes
    // exactly r_local (keys descending + unique).
    int rank = 0;
    #pragma unroll 8
    for (int t2 = 0; t2 < NTILES; t2++) {
        const unsigned long long* a = sk + t2 * NPT;
        int lo = 0;
        #pragma unroll
        for (int half = 64; half >= 1; half >>= 1) {
            if (a[lo + half - 1] > k) lo += half;
        }
        rank += lo;
    }

    const unsigned int kbit =
        (g_keepmask[myTile * 4 + (r_local >> 5)] >> (r_local & 31)) & 1u;
    const float keepf = kbit ? 1.0f : 0.0f;

    const float4 r0 = g_rec4[e * 2 + 0];
    const float4 r1 = g_rec4[e * 2 + 1];
    float* o = out + (size_t)rank * 7;
    o[0] = r0.x * keepf;
    o[1] = r0.y * keepf;
    o[2] = r0.z * keepf;
    o[3] = r0.w * keepf;
    o[4] = r1.x * keepf;
    o[5] = r1.y * keepf;
    o[6] = r1.z * keepf;
    if (writeKeep) out[RESULT_ELEMS + rank] = keepf;
}

// tail zero-fill only for unexpected out_size layouts
__global__ void fill_zero_kernel(float* __restrict__ out, int start, int end) {
    int i = start + blockIdx.x * blockDim.x + threadIdx.x;
    if (i < end) out[i] = 0.0f;
}

// ---------------------------------------------------------------------------
extern "C" void kernel_launch(void* const* d_in, const int* in_sizes, int n_in,
                              void* d_out, int out_size) {
    const float* tr = (const float*)d_in[0];   // tile_results (64,128,7) f32
    const int*   tp = (const int*)d_in[1];     // tile_positions (64,4) i32
    float* out = (float*)d_out;

    static bool attr_set = false;  // host-side config only; no device state
    if (!attr_set) {
        cudaFuncSetAttribute(rank_scatter_kernel,
                             cudaFuncAttributeMaxDynamicSharedMemorySize,
                             M_TOTAL * (int)sizeof(unsigned long long));
        attr_set = true;
    }

    tile_nms_kernel<<<NTILES, 512>>>(tr, tp);

    const int writeKeep = (out_size >= RESULT_ELEMS + M_TOTAL) ? 1 : 0;
    const int covered = writeKeep ? (RESULT_ELEMS + M_TOTAL) : RESULT_ELEMS;
    if (out_size > covered) {
        const int tail = out_size - covered;
        fill_zero_kernel<<<(tail + 255) / 256, 256>>>(out, covered, out_size);
    }

    rank_scatter_kernel<<<NTILES, NPT, M_TOTAL * sizeof(unsigned long long)>>>(out, writeKeep);
}

// round 3
// speedup vs baseline: 4.1057x; 1.1592x over previous
#include <cuda_runtime.h>

#define M_TOTAL 8192
#define NPT 128
#define NTILES 64
#define RESULT_ELEMS (M_TOTAL * 7)   // 57344
#define THREADS 512

// global scratch (no device allocations allowed)
__device__ unsigned long long g_keys[M_TOTAL];   // per-tile sorted keys
__device__ unsigned long long g_bar = 0;         // grid barrier ticket counter

extern __shared__ unsigned long long sk[];       // 8192 keys = 64KB dynamic

// ---------------------------------------------------------------------------
// Fused kernel: per-tile NMS -> grid barrier -> global rank + scatter
// ---------------------------------------------------------------------------
__global__ void __launch_bounds__(THREADS) fused_nms_kernel(const float* __restrict__ tr,
                                                            const int* __restrict__ tp,
                                                            float* __restrict__ out,
                                                            int writeKeep) {
    const int tile = blockIdx.x;
    const int tid = threadIdx.x;

    __shared__ float s_in[NPT * 7];              // staged raw input rows
    __shared__ unsigned long long s_keyraw[NPT];
    __shared__ float4 s_sbox[NPT];               // sorted class-shifted boxes
    __shared__ float s_area[NPT];                // sorted areas
    __shared__ unsigned int s_validmask[4];      // valid bits (sorted order)
    __shared__ uint4 s_sup[NPT];                 // suppression bitmask rows
    __shared__ float s_rec[NPT][8];              // sorted output records
    __shared__ unsigned int s_kw[4];             // final keep bitmask
    __shared__ int s_rank[NPT];                  // global ranks (accumulated)

    // ---- phase 0: coalesced input stage ----
    {
        const float* base = tr + (size_t)tile * NPT * 7;
        #pragma unroll
        for (int idx = tid; idx < NPT * 7; idx += THREADS) s_in[idx] = base[idx];
    }
    if (tid < 4) s_validmask[tid] = 0;
    if (tid < NPT) s_rank[tid] = 0;
    __syncthreads();

    // ---- phase 1+2: transform, rank-sort, scatter (t < 128) ----
    if (tid < NPT) {
        const int g = tile * NPT + tid;
        const float* r = s_in + tid * 7;
        float b0 = r[0], b1 = r[1], b2 = r[2], b3 = r[3];
        const float score = r[4], labelf = r[5], growth = r[6];
        const float hs = (float)tp[tile * 4 + 0];  // h_start -> cols 1,3
        const float ws = (float)tp[tile * 4 + 2];  // w_start -> cols 0,2
        b0 = fminf(fmaxf(__fadd_rn(b0, ws), 0.0f), 4096.0f);
        b1 = fminf(fmaxf(__fadd_rn(b1, hs), 0.0f), 4096.0f);
        b2 = fminf(fmaxf(__fadd_rn(b2, ws), 0.0f), 4096.0f);
        b3 = fminf(fmaxf(__fadd_rn(b3, hs), 0.0f), 4096.0f);

        const int valid = (score > 0.05f) ? 1 : 0;
        const float skey = valid ? score : __fsub_rn(score, 1e9f);
        unsigned int ob = __float_as_uint(skey);
        ob = (ob & 0x80000000u) ? ~ob : (ob | 0x80000000u);  // monotone float->uint
        // descending score, ties ascending global index (stable argsort)
        const unsigned long long mykey =
            ((unsigned long long)ob << 32) | (unsigned int)(~(unsigned int)g);
        s_keyraw[tid] = mykey;
        __syncwarp();

        const float shift = __fmul_rn(labelf, 8192.0f);      // 2*IMAGE_SIZE
        const float x0  = __fadd_rn(b0, shift);
        const float x1c = __fadd_rn(b1, shift);
        const float x2  = __fadd_rn(b2, shift);
        const float x3  = __fadd_rn(b3, shift);
        const float area = __fmul_rn(__fsub_rn(x2, x0), __fsub_rn(x3, x1c));

        // rank-sort over the 128 keys (needs all warps' s_keyraw -> use a
        // block sync below; but only threads <128 wrote it, and they span
        // warps 0..3 -> syncthreads required)
        __syncthreads();
        int rank = 0;
        #pragma unroll 16
        for (int j = 0; j < NPT; j++) rank += (s_keyraw[j] > mykey) ? 1 : 0;

        s_sbox[rank] = make_float4(x0, x1c, x2, x3);
        s_area[rank] = area;
        atomicOr(&s_validmask[rank >> 5], (unsigned int)valid << (rank & 31));
        s_rec[rank][0] = b0; s_rec[rank][1] = b1; s_rec[rank][2] = b2; s_rec[rank][3] = b3;
        s_rec[rank][4] = score; s_rec[rank][5] = labelf; s_rec[rank][6] = growth;

        g_keys[tile * NPT + rank] = mykey;
        __threadfence();   // publish keys before barrier arrival
    } else {
        __syncthreads();   // match the sync inside the if
    }
    __syncthreads();

    // ---- grid barrier arrival (overlap wait with phases 3-4) ----
    __shared__ unsigned long long s_target;
    if (tid == 0) {
        unsigned long long ticket = atomicAdd(&g_bar, 1ULL);
        s_target = (ticket / NTILES + 1ULL) * NTILES;
    }

    // ---- phase 3: suppression matrix (all 512 threads: (row, 32-col word)) ----
    {
        const int i = tid >> 2;
        const int w = tid & 3;
        const float4 bi = s_sbox[i];
        const float ai = s_area[i];
        unsigned int word = 0;
        #pragma unroll 8
        for (int jj = 0; jj < 32; jj++) {
            const int j = (w << 5) + jj;
            const float4 bj = s_sbox[j];
            const float ltx = fmaxf(bi.x, bj.x), lty = fmaxf(bi.y, bj.y);
            const float rbx = fminf(bi.z, bj.z), rby = fminf(bi.w, bj.w);
            const float wx = fmaxf(__fsub_rn(rbx, ltx), 0.0f);
            const float wy = fmaxf(__fsub_rn(rby, lty), 0.0f);
            const float inter = __fmul_rn(wx, wy);
            const float uni = __fsub_rn(__fadd_rn(ai, s_area[j]), inter);
            const float iou = __fdiv_rn(inter, __fadd_rn(uni, 1e-8f));
            if ((j > i) && (iou > 0.5f)) word |= (1u << jj);
        }
        ((unsigned int*)&s_sup[i])[w] = word;
    }
    __syncthreads();

    // ---- phase 4: sequential greedy reduce (single thread) ----
    if (tid == 0) {
        unsigned int kw0 = s_validmask[0], kw1 = s_validmask[1];
        unsigned int kw2 = s_validmask[2], kw3 = s_validmask[3];
        #pragma unroll 4
        for (int i = 0; i < NPT; i++) {
            unsigned int bit;
            switch (i >> 5) {
                case 0: bit = (kw0 >> (i & 31)) & 1u; break;
                case 1: bit = (kw1 >> (i & 31)) & 1u; break;
                case 2: bit = (kw2 >> (i & 31)) & 1u; break;
                default: bit = (kw3 >> (i & 31)) & 1u; break;
            }
            if (bit) {
                const uint4 s = s_sup[i];
                kw0 &= ~s.x; kw1 &= ~s.y; kw2 &= ~s.z; kw3 &= ~s.w;
            }
        }
        s_kw[0] = kw0; s_kw[1] = kw1; s_kw[2] = kw2; s_kw[3] = kw3;

        // ---- grid barrier wait ----
        const unsigned long long target = s_target;
        while (*(volatile unsigned long long*)&g_bar < target) { }
        __threadfence();
    }
    __syncthreads();

    // ---- phase 5: stage all 8192 keys into smem (coalesced, vectorized) ----
    {
        const ulonglong2* src = (const ulonglong2*)g_keys;
        ulonglong2* dst = (ulonglong2*)sk;
        #pragma unroll
        for (int idx = tid; idx < M_TOTAL / 2; idx += THREADS) dst[idx] = src[idx];
    }
    __syncthreads();

    // ---- phase 6: 4-way-split binary searches ----
    {
        const int e_local = tid & 127;
        const int grp = tid >> 7;                 // 0..3, 16 tiles each
        const unsigned long long k = sk[(tile << 7) + e_local];
        int partial = 0;
        #pragma unroll 4
        for (int t2 = grp * 16; t2 < grp * 16 + 16; t2++) {
            const unsigned long long* a = sk + (t2 << 7);
            int lo = 0;
            #pragma unroll
            for (int half = 64; half >= 1; half >>= 1) {
                if (a[lo + half - 1] > k) lo += half;
            }
            partial += lo;
        }
        atomicAdd(&s_rank[e_local], partial);
    }
    __syncthreads();

    // ---- phase 7: scatter output rows ----
    if (tid < NPT) {
        const int rank = s_rank[tid];
        const unsigned int kbit = (s_kw[tid >> 5] >> (tid & 31)) & 1u;
        const float keepf = kbit ? 1.0f : 0.0f;
        float* o = out + (size_t)rank * 7;
        o[0] = s_rec[tid][0] * keepf;
        o[1] = s_rec[tid][1] * keepf;
        o[2] = s_rec[tid][2] * keepf;
        o[3] = s_rec[tid][3] * keepf;
        o[4] = s_rec[tid][4] * keepf;
        o[5] = s_rec[tid][5] * keepf;
        o[6] = s_rec[tid][6] * keepf;
        if (writeKeep) out[RESULT_ELEMS + rank] = keepf;
    }
}

// tail zero-fill only for unexpected out_size layouts
__global__ void fill_zero_kernel(float* __restrict__ out, int start, int end) {
    int i = start + blockIdx.x * blockDim.x + threadIdx.x;
    if (i < end) out[i] = 0.0f;
}

// ---------------------------------------------------------------------------
extern "C" void kernel_launch(void* const* d_in, const int* in_sizes, int n_in,
                              void* d_out, int out_size) {
    const float* tr = (const float*)d_in[0];   // tile_results (64,128,7) f32
    const int*   tp = (const int*)d_in[1];     // tile_positions (64,4) i32
    float* out = (float*)d_out;

    static bool attr_set = false;  // host-side config only
    if (!attr_set) {
        cudaFuncSetAttribute(fused_nms_kernel,
                             cudaFuncAttributeMaxDynamicSharedMemorySize,
                             M_TOTAL * (int)sizeof(unsigned long long));
        attr_set = true;
    }

    const int writeKeep = (out_size >= RESULT_ELEMS + M_TOTAL) ? 1 : 0;
    const int covered = writeKeep ? (RESULT_ELEMS + M_TOTAL) : RESULT_ELEMS;
    if (out_size > covered) {
        const int tail = out_size - covered;
        fill_zero_kernel<<<(tail + 255) / 256, 256>>>(out, covered, out_size);
    }

    fused_nms_kernel<<<NTILES, THREADS, M_TOTAL * sizeof(unsigned long long)>>>(
        tr, tp, out, writeKeep);
}

// round 4
// speedup vs baseline: 5.3806x; 1.3105x over previous
#include <cuda_runtime.h>

#define M_TOTAL 8192
#define NPT 128
#define NTILES 64
#define RESULT_ELEMS (M_TOTAL * 7)   // 57344
#define THREADS 512

// global scratch (no device allocations allowed)
__device__ unsigned long long g_keys[M_TOTAL];   // per-tile sorted keys
__device__ unsigned long long g_bar = 0;         // grid barrier ticket counter

extern __shared__ unsigned long long sk[];       // 8192 keys = 64KB dynamic

// ---------------------------------------------------------------------------
__global__ void __launch_bounds__(THREADS) fused_nms_kernel(const float* __restrict__ tr,
                                                            const int* __restrict__ tp,
                                                            float* __restrict__ out,
                                                            int writeKeep) {
    const int tile = blockIdx.x;
    const int tid = threadIdx.x;

    __shared__ float s_in[NPT * 7];              // staged raw input rows
    __shared__ unsigned long long s_keyraw[NPT];
    __shared__ float4 s_sbox[NPT];               // sorted class-shifted boxes
    __shared__ float s_area[NPT];                // sorted areas
    __shared__ unsigned int s_validmask[4];      // valid bits (sorted order)
    __shared__ unsigned int s_rownz[4];          // rows with any suppression bit
    __shared__ uint4 s_sup[NPT];                 // suppression bitmask rows
    __shared__ float s_rec[NPT][8];              // sorted output records
    __shared__ unsigned int s_kw[4];             // final keep bitmask
    __shared__ int s_rank[NPT];                  // global ranks (accumulated)
    __shared__ unsigned long long s_target;

    // ---- phase 0: coalesced vectorized input stage (224 float4) ----
    {
        const float4* src = (const float4*)(tr + (size_t)tile * NPT * 7);
        float4* dst = (float4*)s_in;
        if (tid < NPT * 7 / 4) dst[tid] = src[tid];
    }
    if (tid < 4) { s_validmask[tid] = 0; s_rownz[tid] = 0; }
    if (tid < NPT) s_rank[tid] = 0;
    __syncthreads();

    // ---- phase 1+2: transform, rank-sort, publish keys (t < 128) ----
    if (tid < NPT) {
        const int g = tile * NPT + tid;
        const float* r = s_in + tid * 7;
        float b0 = r[0], b1 = r[1], b2 = r[2], b3 = r[3];
        const float score = r[4], labelf = r[5], growth = r[6];
        const float hs = (float)tp[tile * 4 + 0];  // h_start -> cols 1,3
        const float ws = (float)tp[tile * 4 + 2];  // w_start -> cols 0,2
        b0 = fminf(fmaxf(__fadd_rn(b0, ws), 0.0f), 4096.0f);
        b1 = fminf(fmaxf(__fadd_rn(b1, hs), 0.0f), 4096.0f);
        b2 = fminf(fmaxf(__fadd_rn(b2, ws), 0.0f), 4096.0f);
        b3 = fminf(fmaxf(__fadd_rn(b3, hs), 0.0f), 4096.0f);

        const int valid = (score > 0.05f) ? 1 : 0;
        const float skey = valid ? score : __fsub_rn(score, 1e9f);
        unsigned int ob = __float_as_uint(skey);
        ob = (ob & 0x80000000u) ? ~ob : (ob | 0x80000000u);  // monotone float->uint
        // descending score, ties ascending global index (stable argsort)
        const unsigned long long mykey =
            ((unsigned long long)ob << 32) | (unsigned int)(~(unsigned int)g);
        s_keyraw[tid] = mykey;

        const float shift = __fmul_rn(labelf, 8192.0f);      // 2*IMAGE_SIZE
        const float x0  = __fadd_rn(b0, shift);
        const float x1c = __fadd_rn(b1, shift);
        const float x2  = __fadd_rn(b2, shift);
        const float x3  = __fadd_rn(b3, shift);
        const float area = __fmul_rn(__fsub_rn(x2, x0), __fsub_rn(x3, x1c));

        __syncthreads();   // s_keyraw complete (warps 0..3)
        int rank = 0;
        #pragma unroll 16
        for (int j = 0; j < NPT; j++) rank += (s_keyraw[j] > mykey) ? 1 : 0;

        s_sbox[rank] = make_float4(x0, x1c, x2, x3);
        s_area[rank] = area;
        atomicOr(&s_validmask[rank >> 5], (unsigned int)valid << (rank & 31));
        s_rec[rank][0] = b0; s_rec[rank][1] = b1; s_rec[rank][2] = b2; s_rec[rank][3] = b3;
        s_rec[rank][4] = score; s_rec[rank][5] = labelf; s_rec[rank][6] = growth;

        g_keys[tile * NPT + rank] = mykey;   // plain STG; ordered by bar + release below
    } else {
        __syncthreads();   // match sync inside branch
    }
    __syncthreads();

    // ---- grid barrier arrival: CG-style single release-atomic ----
    if (tid == 0) {
        unsigned long long ticket;
        asm volatile("atom.release.gpu.add.u64 %0, [%1], %2;"
                     : "=l"(ticket) : "l"(&g_bar), "l"(1ULL) : "memory");
        s_target = (ticket / NTILES + 1ULL) * NTILES;
    }

    // ---- phase 3: suppression matrix + row-nonzero mask (512 threads) ----
    {
        const int i = tid >> 2;
        const int w = tid & 3;
        const float4 bi = s_sbox[i];
        const float ai = s_area[i];
        unsigned int word = 0;
        #pragma unroll 8
        for (int jj = 0; jj < 32; jj++) {
            const int j = (w << 5) + jj;
            const float4 bj = s_sbox[j];
            const float ltx = fmaxf(bi.x, bj.x), lty = fmaxf(bi.y, bj.y);
            const float rbx = fminf(bi.z, bj.z), rby = fminf(bi.w, bj.w);
            const float wx = fmaxf(__fsub_rn(rbx, ltx), 0.0f);
            const float wy = fmaxf(__fsub_rn(rby, lty), 0.0f);
            const float inter = __fmul_rn(wx, wy);
            const float uni = __fsub_rn(__fadd_rn(ai, s_area[j]), inter);
            const float iou = __fdiv_rn(inter, __fadd_rn(uni, 1e-8f));
            if ((j > i) && (iou > 0.5f)) word |= (1u << jj);
        }
        ((unsigned int*)&s_sup[i])[w] = word;

        // warp covers rows [wid*8, wid*8+8); 4 lanes per row
        const unsigned int nz = __ballot_sync(0xFFFFFFFFu, word != 0);
        if ((tid & 31) == 0 && nz) {
            unsigned int rb = 0;
            #pragma unroll
            for (int rr = 0; rr < 8; rr++)
                if ((nz >> (rr * 4)) & 0xFu) rb |= (1u << rr);
            const int wid = tid >> 5;
            atomicOr(&s_rownz[wid >> 2], rb << ((wid & 3) * 8));
        }
    }
    __syncthreads();

    // ---- phase 4: sparse greedy reduce (single thread, ffs over active rows) ----
    if (tid == 0) {
        unsigned int kw[4];
        kw[0] = s_validmask[0]; kw[1] = s_validmask[1];
        kw[2] = s_validmask[2]; kw[3] = s_validmask[3];
        #pragma unroll
        for (int w = 0; w < 4; w++) {
            const unsigned int rz = s_rownz[w];
            unsigned int act = kw[w] & rz;
            while (act) {
                const int ib = __ffs(act) - 1;
                const uint4 s = s_sup[w * 32 + ib];
                kw[0] &= ~s.x; kw[1] &= ~s.y; kw[2] &= ~s.z; kw[3] &= ~s.w;
                act = kw[w] & rz & (0xFFFFFFFEu << ib);
            }
        }
        s_kw[0] = kw[0]; s_kw[1] = kw[1]; s_kw[2] = kw[2]; s_kw[3] = kw[3];

        // ---- grid barrier wait (acquire poll) ----
        const unsigned long long target = s_target;
        unsigned long long cur;
        do {
            asm volatile("ld.acquire.gpu.u64 %0, [%1];"
                         : "=l"(cur) : "l"(&g_bar) : "memory");
        } while (cur < target);
    }
    __syncthreads();

    // ---- phase 5: stage all 8192 keys into smem (L2 loads, vectorized) ----
    {
        const ulonglong2* src = (const ulonglong2*)g_keys;
        ulonglong2* dst = (ulonglong2*)sk;
        #pragma unroll
        for (int idx = tid; idx < M_TOTAL / 2; idx += THREADS) dst[idx] = __ldcg(src + idx);
    }
    __syncthreads();

    // ---- phase 6: 16-state interleaved binary searches (4 threads/element) ----
    {
        const int e_local = tid & 127;
        const int grp = tid >> 7;                 // 0..3, 16 tiles each
        const unsigned long long k = sk[(tile << 7) + e_local];
        const unsigned long long* base = sk + (grp << 11);  // grp*16 tiles * 128

        int lo[16];
        #pragma unroll
        for (int t = 0; t < 16; t++) lo[t] = 0;
        #pragma unroll
        for (int half = 64; half >= 1; half >>= 1) {
            #pragma unroll
            for (int t = 0; t < 16; t++) {
                if (base[(t << 7) + lo[t] + half - 1] > k) lo[t] += half;
            }
        }
        int partial = 0;
        #pragma unroll
        for (int t = 0; t < 16; t++) partial += lo[t];
        atomicAdd(&s_rank[e_local], partial);
    }
    __syncthreads();

    // ---- phase 7: scatter output rows ----
    if (tid < NPT) {
        const int rank = s_rank[tid];
        const unsigned int kbit = (s_kw[tid >> 5] >> (tid & 31)) & 1u;
        const float keepf = kbit ? 1.0f : 0.0f;
        float* o = out + (size_t)rank * 7;
        o[0] = s_rec[tid][0] * keepf;
        o[1] = s_rec[tid][1] * keepf;
        o[2] = s_rec[tid][2] * keepf;
        o[3] = s_rec[tid][3] * keepf;
        o[4] = s_rec[tid][4] * keepf;
        o[5] = s_rec[tid][5] * keepf;
        o[6] = s_rec[tid][6] * keepf;
        if (writeKeep) out[RESULT_ELEMS + rank] = keepf;
    }
}

// tail zero-fill only for unexpected out_size layouts
__global__ void fill_zero_kernel(float* __restrict__ out, int start, int end) {
    int i = start + blockIdx.x * blockDim.x + threadIdx.x;
    if (i < end) out[i] = 0.0f;
}

// ---------------------------------------------------------------------------
extern "C" void kernel_launch(void* const* d_in, const int* in_sizes, int n_in,
                              void* d_out, int out_size) {
    const float* tr = (const float*)d_in[0];   // tile_results (64,128,7) f32
    const int*   tp = (const int*)d_in[1];     // tile_positions (64,4) i32
    float* out = (float*)d_out;

    static bool attr_set = false;  // host-side config only
    if (!attr_set) {
        cudaFuncSetAttribute(fused_nms_kernel,
                             cudaFuncAttributeMaxDynamicSharedMemorySize,
                             M_TOTAL * (int)sizeof(unsigned long long));
        attr_set = true;
    }

    const int writeKeep = (out_size >= RESULT_ELEMS + M_TOTAL) ? 1 : 0;
    const int covered = writeKeep ? (RESULT_ELEMS + M_TOTAL) : RESULT_ELEMS;
    if (out_size > covered) {
        const int tail = out_size - covered;
        fill_zero_kernel<<<(tail + 255) / 256, 256>>>(out, covered, out_size);
    }

    fused_nms_kernel<<<NTILES, THREADS, M_TOTAL * sizeof(unsigned long long)>>>(
        tr, tp, out, writeKeep);
}

// round 5
// speedup vs baseline: 5.4535x; 1.0135x over previous
#include <cuda_runtime.h>

#define M_TOTAL 8192
#define NPT 128
#define NTILES 64
#define RESULT_ELEMS (M_TOTAL * 7)   // 57344
#define THREADS 1024

// global scratch (no device allocations allowed)
__device__ unsigned long long g_keys[M_TOTAL];   // per-tile sorted keys
__device__ unsigned long long g_bar = 0;         // grid barrier ticket counter

extern __shared__ unsigned long long sk[];       // 8192 keys = 64KB dynamic

// ---------------------------------------------------------------------------
__global__ void __launch_bounds__(THREADS) fused_nms_kernel(const float* __restrict__ tr,
                                                            const int* __restrict__ tp,
                                                            float* __restrict__ out,
                                                            int writeKeep) {
    const int tile = blockIdx.x;
    const int tid = threadIdx.x;

    __shared__ float s_in[NPT * 7];              // staged raw input rows
    __shared__ unsigned long long s_keyraw[NPT];
    __shared__ float4 s_sbox[NPT];               // sorted class-shifted boxes
    __shared__ float s_area[NPT];                // sorted areas
    __shared__ unsigned int s_validmask[4];      // valid bits (sorted order)
    __shared__ unsigned int s_rownz[4];          // rows with any suppression bit
    __shared__ uint4 s_sup[NPT];                 // suppression bitmask rows
    __shared__ float s_rec[NPT][8];              // sorted output records
    __shared__ unsigned int s_kw[4];             // final keep bitmask
    __shared__ int s_rank[NPT];                  // global ranks (accumulated)
    __shared__ unsigned long long s_target;

    // ---- phase 0: coalesced vectorized input stage (224 float4) ----
    {
        const float4* src = (const float4*)(tr + (size_t)tile * NPT * 7);
        float4* dst = (float4*)s_in;
        if (tid < NPT * 7 / 4) dst[tid] = src[tid];
    }
    if (tid < 4) { s_validmask[tid] = 0; s_rownz[tid] = 0; }
    if (tid < NPT) s_rank[tid] = 0;
    __syncthreads();

    // ---- phase 1: transform, publish raw key (t < 128) ----
    const bool active = (tid < NPT);
    float b0, b1, b2, b3, score, labelf, growth, x0, x1c, x2, x3, area;
    unsigned long long mykey = 0;
    int valid = 0;
    if (active) {
        const int g = tile * NPT + tid;
        const float* r = s_in + tid * 7;
        b0 = r[0]; b1 = r[1]; b2 = r[2]; b3 = r[3];
        score = r[4]; labelf = r[5]; growth = r[6];
        const float hs = (float)tp[tile * 4 + 0];  // h_start -> cols 1,3
        const float ws = (float)tp[tile * 4 + 2];  // w_start -> cols 0,2
        b0 = fminf(fmaxf(__fadd_rn(b0, ws), 0.0f), 4096.0f);
        b1 = fminf(fmaxf(__fadd_rn(b1, hs), 0.0f), 4096.0f);
        b2 = fminf(fmaxf(__fadd_rn(b2, ws), 0.0f), 4096.0f);
        b3 = fminf(fmaxf(__fadd_rn(b3, hs), 0.0f), 4096.0f);

        valid = (score > 0.05f) ? 1 : 0;
        const float skey = valid ? score : __fsub_rn(score, 1e9f);
        unsigned int ob = __float_as_uint(skey);
        ob = (ob & 0x80000000u) ? ~ob : (ob | 0x80000000u);  // monotone float->uint
        // descending score, ties ascending global index (stable argsort)
        mykey = ((unsigned long long)ob << 32) | (unsigned int)(~(unsigned int)g);
        s_keyraw[tid] = mykey;

        const float shift = __fmul_rn(labelf, 8192.0f);      // 2*IMAGE_SIZE
        x0  = __fadd_rn(b0, shift);
        x1c = __fadd_rn(b1, shift);
        x2  = __fadd_rn(b2, shift);
        x3  = __fadd_rn(b3, shift);
        area = __fmul_rn(__fsub_rn(x2, x0), __fsub_rn(x3, x1c));
    }
    __syncthreads();

    // ---- phase 2: rank-sort + scatter into sorted arrays ----
    if (active) {
        int rank = 0;
        #pragma unroll 16
        for (int j = 0; j < NPT; j++) rank += (s_keyraw[j] > mykey) ? 1 : 0;

        s_sbox[rank] = make_float4(x0, x1c, x2, x3);
        s_area[rank] = area;
        atomicOr(&s_validmask[rank >> 5], (unsigned int)valid << (rank & 31));
        s_rec[rank][0] = b0; s_rec[rank][1] = b1; s_rec[rank][2] = b2; s_rec[rank][3] = b3;
        s_rec[rank][4] = score; s_rec[rank][5] = labelf; s_rec[rank][6] = growth;

        g_keys[tile * NPT + rank] = mykey;   // ordered by bar.sync + release atom below
    }
    __syncthreads();

    // ---- grid barrier arrival: single release-atomic per CTA ----
    if (tid == 0) {
        unsigned long long ticket;
        asm volatile("atom.release.gpu.add.u64 %0, [%1], %2;"
                     : "=l"(ticket) : "l"(&g_bar), "l"(1ULL) : "memory");
        s_target = (ticket / NTILES + 1ULL) * NTILES;
    }

    // ---- phase 3: suppression matrix; thread = (row, 16-col halfword) ----
    {
        const int i = tid >> 3;
        const int w = tid & 7;
        const float4 bi = s_sbox[i];
        const float ai = s_area[i];
        unsigned int half16 = 0;
        #pragma unroll 4
        for (int jj = 0; jj < 16; jj++) {
            const int j = (w << 4) + jj;
            const float4 bj = s_sbox[j];
            const float ltx = fmaxf(bi.x, bj.x), lty = fmaxf(bi.y, bj.y);
            const float rbx = fminf(bi.z, bj.z), rby = fminf(bi.w, bj.w);
            const float wx = fmaxf(__fsub_rn(rbx, ltx), 0.0f);
            const float wy = fmaxf(__fsub_rn(rby, lty), 0.0f);
            // inter==0 (wx==0||wy==0) -> iou==0 exactly (union>0): never suppresses.
            if ((j > i) && (wx > 0.0f) && (wy > 0.0f)) {
                const float inter = __fmul_rn(wx, wy);
                const float uni = __fsub_rn(__fadd_rn(ai, s_area[j]), inter);
                const float iou = __fdiv_rn(inter, __fadd_rn(uni, 1e-8f));
                if (iou > 0.5f) half16 |= (1u << jj);
            }
        }
        // combine adjacent halfwords (lane parity == w parity)
        const unsigned int other = __shfl_xor_sync(0xFFFFFFFFu, half16, 1);
        if ((w & 1) == 0) {
            ((unsigned int*)&s_sup[i])[w >> 1] = half16 | (other << 16);
        }
        // row-nonzero bits: warp covers rows [wid*4, wid*4+4), 8 lanes per row
        const unsigned int nz = __ballot_sync(0xFFFFFFFFu, half16 != 0);
        if ((tid & 31) == 0 && nz) {
            unsigned int rb = 0;
            #pragma unroll
            for (int q = 0; q < 4; q++)
                if ((nz >> (q * 8)) & 0xFFu) rb |= (1u << q);
            const int wid = tid >> 5;
            atomicOr(&s_rownz[wid >> 3], rb << ((wid & 7) * 4));
        }
    }
    __syncthreads();

    // ---- phase 4: sparse greedy reduce (single thread, ffs over active rows) ----
    if (tid == 0) {
        unsigned int kw[4];
        kw[0] = s_validmask[0]; kw[1] = s_validmask[1];
        kw[2] = s_validmask[2]; kw[3] = s_validmask[3];
        #pragma unroll
        for (int w = 0; w < 4; w++) {
            const unsigned int rz = s_rownz[w];
            unsigned int act = kw[w] & rz;
            while (act) {
                const int ib = __ffs(act) - 1;
                const uint4 s = s_sup[w * 32 + ib];
                kw[0] &= ~s.x; kw[1] &= ~s.y; kw[2] &= ~s.z; kw[3] &= ~s.w;
                act = kw[w] & rz & (0xFFFFFFFEu << ib);
            }
        }
        s_kw[0] = kw[0]; s_kw[1] = kw[1]; s_kw[2] = kw[2]; s_kw[3] = kw[3];

        // ---- grid barrier wait (acquire poll) ----
        const unsigned long long target = s_target;
        unsigned long long cur;
        do {
            asm volatile("ld.acquire.gpu.u64 %0, [%1];"
                         : "=l"(cur) : "l"(&g_bar) : "memory");
        } while (cur < target);
    }
    __syncthreads();

    // ---- phase 5: stage all 8192 keys into smem (L2 loads, vectorized) ----
    {
        const ulonglong2* src = (const ulonglong2*)g_keys;
        ulonglong2* dst = (ulonglong2*)sk;
        #pragma unroll
        for (int idx = tid; idx < M_TOTAL / 2; idx += THREADS) dst[idx] = __ldcg(src + idx);
    }
    __syncthreads();

    // ---- phase 6: 8-state interleaved binary searches (8 threads/element) ----
    {
        const int e_local = tid & 127;
        const int grp = tid >> 7;                 // 0..7, 8 tiles each
        const unsigned long long k = sk[(tile << 7) + e_local];
        const unsigned long long* base = sk + (grp << 10);  // grp*8 tiles * 128

        int lo[8];
        #pragma unroll
        for (int t = 0; t < 8; t++) lo[t] = 0;
        #pragma unroll
        for (int half = 64; half >= 1; half >>= 1) {
            #pragma unroll
            for (int t = 0; t < 8; t++) {
                if (base[(t << 7) + lo[t] + half - 1] > k) lo[t] += half;
            }
        }
        int partial = lo[0] + lo[1] + lo[2] + lo[3] + lo[4] + lo[5] + lo[6] + lo[7];
        atomicAdd(&s_rank[e_local], partial);
    }
    __syncthreads();

    // ---- phase 7: scatter output rows ----
    if (active) {
        const int rank = s_rank[tid];
        const unsigned int kbit = (s_kw[tid >> 5] >> (tid & 31)) & 1u;
        const float keepf = kbit ? 1.0f : 0.0f;
        float* o = out + (size_t)rank * 7;
        o[0] = s_rec[tid][0] * keepf;
        o[1] = s_rec[tid][1] * keepf;
        o[2] = s_rec[tid][2] * keepf;
        o[3] = s_rec[tid][3] * keepf;
        o[4] = s_rec[tid][4] * keepf;
        o[5] = s_rec[tid][5] * keepf;
        o[6] = s_rec[tid][6] * keepf;
        if (writeKeep) out[RESULT_ELEMS + rank] = keepf;
    }
}

// tail zero-fill only for unexpected out_size layouts
__global__ void fill_zero_kernel(float* __restrict__ out, int start, int end) {
    int i = start + blockIdx.x * blockDim.x + threadIdx.x;
    if (i < end) out[i] = 0.0f;
}

// ---------------------------------------------------------------------------
extern "C" void kernel_launch(void* const* d_in, const int* in_sizes, int n_in,
                              void* d_out, int out_size) {
    const float* tr = (const float*)d_in[0];   // tile_results (64,128,7) f32
    const int*   tp = (const int*)d_in[1];     // tile_positions (64,4) i32
    float* out = (float*)d_out;

    static bool attr_set = false;  // host-side config only
    if (!attr_set) {
        cudaFuncSetAttribute(fused_nms_kernel,
                             cudaFuncAttributeMaxDynamicSharedMemorySize,
                             M_TOTAL * (int)sizeof(unsigned long long));
        attr_set = true;
    }

    const int writeKeep = (out_size >= RESULT_ELEMS + M_TOTAL) ? 1 : 0;
    const int covered = writeKeep ? (RESULT_ELEMS + M_TOTAL) : RESULT_ELEMS;
    if (out_size > covered) {
        const int tail = out_size - covered;
        fill_zero_kernel<<<(tail + 255) / 256, 256>>>(out, covered, out_size);
    }

    fused_nms_kernel<<<NTILES, THREADS, M_TOTAL * sizeof(unsigned long long)>>>(
        tr, tp, out, writeKeep);
}

// round 6
// speedup vs baseline: 6.0243x; 1.1047x over previous
#include <cuda_runtime.h>

#define M_TOTAL 8192
#define NPT 128
#define NTILES 64
#define RESULT_ELEMS (M_TOTAL * 7)   // 57344
#define THREADS 1024

// global scratch (no device allocations allowed)
__device__ unsigned int g_keys32[M_TOTAL];       // per-tile sorted key hi (score part)
__device__ unsigned int g_keyslo[M_TOTAL];       // per-tile sorted key lo (~index part)
__device__ unsigned long long g_bar = 0;         // grid barrier ticket counter

// dynamic smem: [0:8192) uint sk32, [8192:16384) uint sklo  (64KB)
extern __shared__ unsigned int s_dyn[];

// ---------------------------------------------------------------------------
__global__ void __launch_bounds__(THREADS) fused_nms_kernel(const float* __restrict__ tr,
                                                            const int* __restrict__ tp,
                                                            float* __restrict__ out,
                                                            int writeKeep) {
    const int tile = blockIdx.x;
    const int tid = threadIdx.x;

    unsigned int* sk32 = s_dyn;
    unsigned int* sklo = s_dyn + M_TOTAL;

    __shared__ float s_in[NPT * 7];              // staged raw input rows
    __shared__ unsigned long long s_keyraw[NPT];
    __shared__ float4 s_sbox[NPT];               // sorted class-shifted boxes
    __shared__ float s_area[NPT];                // sorted areas
    __shared__ unsigned int s_validmask[4];      // valid bits (sorted order)
    __shared__ unsigned int s_rownz[4];          // rows with any suppression bit
    __shared__ uint4 s_sup[NPT];                 // suppression bitmask rows
    __shared__ float s_rec[NPT][8];              // sorted output records
    __shared__ unsigned int s_kw[4];             // final keep bitmask
    __shared__ int s_rank[NPT];                  // global ranks (accumulated)
    __shared__ unsigned long long s_target;

    // ---- phase 0: stage input + zero sup matrix ----
    {
        const float4* src = (const float4*)(tr + (size_t)tile * NPT * 7);
        float4* dst = (float4*)s_in;
        if (tid < NPT * 7 / 4) dst[tid] = src[tid];
    }
    if (tid < 512) ((unsigned int*)s_sup)[tid] = 0;   // 128 rows x 4 words
    if (tid < 4) { s_validmask[tid] = 0; s_rownz[tid] = 0; }
    if (tid < NPT) s_rank[tid] = 0;
    __syncthreads();

    // ---- phase 1: transform, publish raw key (t < 128) ----
    const bool active = (tid < NPT);
    float b0, b1, b2, b3, score, labelf, growth, x0, x1c, x2, x3, area;
    unsigned long long mykey = 0;
    int valid = 0;
    if (active) {
        const int g = tile * NPT + tid;
        const float* r = s_in + tid * 7;
        b0 = r[0]; b1 = r[1]; b2 = r[2]; b3 = r[3];
        score = r[4]; labelf = r[5]; growth = r[6];
        const float hs = (float)tp[tile * 4 + 0];  // h_start -> cols 1,3
        const float ws = (float)tp[tile * 4 + 2];  // w_start -> cols 0,2
        b0 = fminf(fmaxf(__fadd_rn(b0, ws), 0.0f), 4096.0f);
        b1 = fminf(fmaxf(__fadd_rn(b1, hs), 0.0f), 4096.0f);
        b2 = fminf(fmaxf(__fadd_rn(b2, ws), 0.0f), 4096.0f);
        b3 = fminf(fmaxf(__fadd_rn(b3, hs), 0.0f), 4096.0f);

        valid = (score > 0.05f) ? 1 : 0;
        const float skey = valid ? score : __fsub_rn(score, 1e9f);
        unsigned int ob = __float_as_uint(skey);
        ob = (ob & 0x80000000u) ? ~ob : (ob | 0x80000000u);  // monotone float->uint
        // descending score, ties ascending global index (stable argsort)
        mykey = ((unsigned long long)ob << 32) | (unsigned int)(~(unsigned int)g);
        s_keyraw[tid] = mykey;

        const float shift = __fmul_rn(labelf, 8192.0f);      // 2*IMAGE_SIZE
        x0  = __fadd_rn(b0, shift);
        x1c = __fadd_rn(b1, shift);
        x2  = __fadd_rn(b2, shift);
        x3  = __fadd_rn(b3, shift);
        area = __fmul_rn(__fsub_rn(x2, x0), __fsub_rn(x3, x1c));
    }
    __syncthreads();

    // ---- phase 2: rank-sort + scatter into sorted arrays ----
    if (active) {
        int rank = 0;
        #pragma unroll 16
        for (int j = 0; j < NPT; j++) rank += (s_keyraw[j] > mykey) ? 1 : 0;

        s_sbox[rank] = make_float4(x0, x1c, x2, x3);
        s_area[rank] = area;
        atomicOr(&s_validmask[rank >> 5], (unsigned int)valid << (rank & 31));
        s_rec[rank][0] = b0; s_rec[rank][1] = b1; s_rec[rank][2] = b2; s_rec[rank][3] = b3;
        s_rec[rank][4] = score; s_rec[rank][5] = labelf; s_rec[rank][6] = growth;

        g_keys32[tile * NPT + rank] = (unsigned int)(mykey >> 32);
        g_keyslo[tile * NPT + rank] = (unsigned int)mykey;
    }
    __syncthreads();

    // ---- grid barrier arrival: single release-atomic per CTA ----
    if (tid == 0) {
        unsigned long long ticket;
        asm volatile("atom.release.gpu.add.u64 %0, [%1], %2;"
                     : "=l"(ticket) : "l"(&g_bar), "l"(1ULL) : "memory");
        s_target = (ticket / NTILES + 1ULL) * NTILES;
    }

    // ---- phase 3: suppression matrix; warp-uniform j (broadcast LDS) ----
    {
        const int i = tid & 127;              // row (lanes consecutive)
        const int w = tid >> 7;               // col group 0..7 (warp-uniform)
        unsigned int half16 = 0;
        if (i < ((w + 1) << 4)) {             // col group has some j > i
            const float4 bi = s_sbox[i];
            const float ai = s_area[i];
            #pragma unroll 4
            for (int jj = 0; jj < 16; jj++) {
                const int j = (w << 4) + jj;  // uniform across warp -> broadcast
                const float4 bj = s_sbox[j];
                const float aj = s_area[j];
                const float ltx = fmaxf(bi.x, bj.x), lty = fmaxf(bi.y, bj.y);
                const float rbx = fminf(bi.z, bj.z), rby = fminf(bi.w, bj.w);
                const float wx = fmaxf(__fsub_rn(rbx, ltx), 0.0f);
                const float wy = fmaxf(__fsub_rn(rby, lty), 0.0f);
                // inter==0 -> iou==0 exactly (union>0): never suppresses.
                if ((j > i) && (wx > 0.0f) && (wy > 0.0f)) {
                    const float inter = __fmul_rn(wx, wy);
                    const float uni = __fsub_rn(__fadd_rn(ai, aj), inter);
                    const float iou = __fdiv_rn(inter, __fadd_rn(uni, 1e-8f));
                    if (iou > 0.5f) half16 |= (1u << jj);
                }
            }
        }
        if (half16)
            atomicOr(&((unsigned int*)&s_sup[i])[w >> 1], half16 << ((w & 1) * 16));
        // warp wid covers rows [(wid&3)*32, +32), lane l <-> row bit l
        const unsigned int nz = __ballot_sync(0xFFFFFFFFu, half16 != 0);
        if ((tid & 31) == 0 && nz) atomicOr(&s_rownz[(tid >> 5) & 3], nz);
    }
    __syncthreads();

    // ---- phase 4: sparse greedy reduce (single thread, ffs over active rows) ----
    if (tid == 0) {
        unsigned int kw[4];
        kw[0] = s_validmask[0]; kw[1] = s_validmask[1];
        kw[2] = s_validmask[2]; kw[3] = s_validmask[3];
        #pragma unroll
        for (int w = 0; w < 4; w++) {
            const unsigned int rz = s_rownz[w];
            unsigned int act = kw[w] & rz;
            while (act) {
                const int ib = __ffs(act) - 1;
                const uint4 s = s_sup[w * 32 + ib];
                kw[0] &= ~s.x; kw[1] &= ~s.y; kw[2] &= ~s.z; kw[3] &= ~s.w;
                act = kw[w] & rz & (0xFFFFFFFEu << ib);
            }
        }
        s_kw[0] = kw[0]; s_kw[1] = kw[1]; s_kw[2] = kw[2]; s_kw[3] = kw[3];

        // ---- grid barrier wait (acquire poll) ----
        const unsigned long long target = s_target;
        unsigned long long cur;
        do {
            asm volatile("ld.acquire.gpu.u64 %0, [%1];"
                         : "=l"(cur) : "l"(&g_bar) : "memory");
        } while (cur < target);
    }
    __syncthreads();

    // ---- phase 5: stage all keys into smem (vectorized L2 loads) ----
    {
        const uint4* s32 = (const uint4*)g_keys32;
        const uint4* slo = (const uint4*)g_keyslo;
        uint4* d32 = (uint4*)sk32;
        uint4* dlo = (uint4*)sklo;
        #pragma unroll
        for (int idx = tid; idx < M_TOTAL / 4; idx += THREADS) {
            d32[idx] = __ldcg(s32 + idx);
            dlo[idx] = __ldcg(slo + idx);
        }
    }
    __syncthreads();

    // ---- phase 6: 8-state interleaved 32-bit binary searches + tie walk ----
    {
        const int e_local = tid & 127;
        const int grp = tid >> 7;                 // 0..7, 8 tiles each
        const unsigned int k32 = sk32[(tile << 7) + e_local];
        const unsigned int klo = sklo[(tile << 7) + e_local];
        const unsigned int* base = sk32 + (grp << 10);   // 8 tiles * 128

        int lo[8];
        #pragma unroll
        for (int t = 0; t < 8; t++) lo[t] = 0;
        #pragma unroll
        for (int half = 64; half >= 1; half >>= 1) {
            #pragma unroll
            for (int t = 0; t < 8; t++) {
                if (base[(t << 7) + lo[t] + half - 1] > k32) lo[t] += half;
            }
        }
        int partial = 0;
        #pragma unroll
        for (int t = 0; t < 8; t++) {
            int j = lo[t];
            partial += j;
            // tie walk: keys with equal hi, ordered by lo descending in sort;
            // those with bigger lo word precede me in 64-bit order.
            const int tb = (grp << 10) + (t << 7);
            while (j < NPT && sk32[tb + j] == k32) {
                partial += (sklo[tb + j] > klo) ? 1 : 0;
                j++;
            }
        }
        atomicAdd(&s_rank[e_local], partial);
    }
    __syncthreads();

    // ---- phase 7: scatter output rows ----
    if (active) {
        const int rank = s_rank[tid];
        const unsigned int kbit = (s_kw[tid >> 5] >> (tid & 31)) & 1u;
        const float keepf = kbit ? 1.0f : 0.0f;
        float* o = out + (size_t)rank * 7;
        o[0] = s_rec[tid][0] * keepf;
        o[1] = s_rec[tid][1] * keepf;
        o[2] = s_rec[tid][2] * keepf;
        o[3] = s_rec[tid][3] * keepf;
        o[4] = s_rec[tid][4] * keepf;
        o[5] = s_rec[tid][5] * keepf;
        o[6] = s_rec[tid][6] * keepf;
        if (writeKeep) out[RESULT_ELEMS + rank] = keepf;
    }
}

// tail zero-fill only for unexpected out_size layouts
__global__ void fill_zero_kernel(float* __restrict__ out, int start, int end) {
    int i = start + blockIdx.x * blockDim.x + threadIdx.x;
    if (i < end) out[i] = 0.0f;
}

// ---------------------------------------------------------------------------
extern "C" void kernel_launch(void* const* d_in, const int* in_sizes, int n_in,
                              void* d_out, int out_size) {
    const float* tr = (const float*)d_in[0];   // tile_results (64,128,7) f32
    const int*   tp = (const int*)d_in[1];     // tile_positions (64,4) i32
    float* out = (float*)d_out;

    static bool attr_set = false;  // host-side config only
    if (!attr_set) {
        cudaFuncSetAttribute(fused_nms_kernel,
                             cudaFuncAttributeMaxDynamicSharedMemorySize,
                             2 * M_TOTAL * (int)sizeof(unsigned int));
        attr_set = true;
    }

    const int writeKeep = (out_size >= RESULT_ELEMS + M_TOTAL) ? 1 : 0;
    const int covered = writeKeep ? (RESULT_ELEMS + M_TOTAL) : RESULT_ELEMS;
    if (out_size > covered) {
        const int tail = out_size - covered;
        fill_zero_kernel<<<(tail + 255) / 256, 256>>>(out, covered, out_size);
    }

    fused_nms_kernel<<<NTILES, THREADS, 2 * M_TOTAL * sizeof(unsigned int)>>>(
        tr, tp, out, writeKeep);
}